// round 9
// baseline (speedup 1.0000x reference)
#include <cuda_runtime.h>
#include <cstdint>

// TT embedding lookup: single-kernel, self-scheduling, bulk-async 3-stage ring.
//   P=(216,216,216), Q=(2,4,2), R=(128,128), tables=2, batch=1024
//   out[t,b, q0*8+q1*2+q2] = sum_{r0,r1} A[q0,r0]*Bm[r0, q1*128+r1]*C[r1,q2]
//
// Grid (432 buckets, 4 passes). Each CTA scans its table's 1024 indices
// (L2-hot) for samples with its i1, takes samples [p*6, p*6+6). The bucket's
// contiguous 256KB core1 slice streams through a 3x8KB smem ring via
// cp.async.bulk (+mbarrier expect_tx, 2 in flight); consumers run packed
// fma.rn.f32x2 off smem with j-paired A broadcasts. launch_bounds(128,6)
// forces 6 CTAs/SM for latency coverage. Exact-KK dispatch, direct stores.

#define P0 216
#define P1 216
#define P2 216
#define TABLES 2
#define SMAXU 6
#define NP 4                    // passes per bucket: covers k <= 24
#define ROWS_PER_STAGE 4
#define NBUF 3
#define NSTAGE_TOT 32           // 128 rows / 4
#define STAGE_BYTES (ROWS_PER_STAGE * 512 * 4)   // 8192
#define LISTCAP 40

// ---- packed f32x2 helpers --------------------------------------------------
__device__ __forceinline__ void ffma2(unsigned long long& d,
                                      unsigned long long a,
                                      unsigned long long b) {
    asm("fma.rn.f32x2 %0, %1, %2, %0;" : "+l"(d) : "l"(a), "l"(b));
}
__device__ __forceinline__ unsigned long long splat2(float v) {
    unsigned long long r;
    unsigned int u = __float_as_uint(v);
    asm("mov.b64 %0, {%1, %1};" : "=l"(r) : "r"(u));
    return r;
}
__device__ __forceinline__ void unpack2(unsigned long long v, float& lo, float& hi) {
    unsigned int a, b;
    asm("mov.b64 {%0, %1}, %2;" : "=r"(a), "=r"(b) : "l"(v));
    lo = __uint_as_float(a);
    hi = __uint_as_float(b);
}

// ---- async-copy / mbarrier helpers ----------------------------------------
__device__ __forceinline__ uint32_t smem_u32(const void* p) {
    return (uint32_t)__cvta_generic_to_shared(p);
}
__device__ __forceinline__ void mbar_init(uint32_t mbar, uint32_t cnt) {
    asm volatile("mbarrier.init.shared.b64 [%0], %1;" :: "r"(mbar), "r"(cnt) : "memory");
}
__device__ __forceinline__ void mbar_expect_tx(uint32_t mbar, uint32_t bytes) {
    asm volatile("mbarrier.arrive.expect_tx.shared.b64 _, [%0], %1;"
                 :: "r"(mbar), "r"(bytes) : "memory");
}
__device__ __forceinline__ void bulk_ld(uint32_t dst, const void* src,
                                        uint32_t bytes, uint32_t mbar) {
    asm volatile("cp.async.bulk.shared::cta.global.mbarrier::complete_tx::bytes "
                 "[%0], [%1], %2, [%3];"
                 :: "r"(dst), "l"(src), "r"(bytes), "r"(mbar) : "memory");
}
__device__ __forceinline__ void mbar_wait(uint32_t mbar, uint32_t parity) {
    asm volatile(
        "{\n\t"
        ".reg .pred P;\n\t"
        "WL_%=:\n\t"
        "mbarrier.try_wait.parity.acquire.cta.shared::cta.b64 P, [%0], %1, 0x989680;\n\t"
        "@!P bra WL_%=;\n\t"
        "}"
        :: "r"(mbar), "r"(parity) : "memory");
}

// ------------------------------------------------------- templated core ----
template <int KK>
__device__ __forceinline__ void run_unit(
    const float* __restrict__ slice,
    const float* __restrict__ sbuf,
    uint32_t sbuf0_u32, uint32_t mb0_u32,
    const unsigned long long (*__restrict__ sA)[SMAXU],
    const int* __restrict__ sSid,
    const int* __restrict__ sI2,
    const float* __restrict__ core2_t,
    float* __restrict__ out,
    int t, int lane, int w)
{
    unsigned long long acc[KK][4];
    #pragma unroll
    for (int j = 0; j < KK; ++j)
        #pragma unroll
        for (int c = 0; c < 4; ++c) acc[j][c] = 0ull;

    int use_b = 0, use_ph = 0;   // consumer ring cursor
    int iss_b = 2;               // producer ring cursor (stages 0,1 pre-issued)

    for (int s = 0; s < NSTAGE_TOT; ++s) {
        mbar_wait(mb0_u32 + 8 * use_b, use_ph);

        const float* buf = sbuf + use_b * (ROWS_PER_STAGE * 512) + 4 * t;
        const int rbase = s * ROWS_PER_STAGE;
        #pragma unroll
        for (int r = 0; r < ROWS_PER_STAGE; ++r) {
            const float4 v = *reinterpret_cast<const float4*>(buf + r * 512);
            const unsigned long long vs0 = splat2(v.x);
            const unsigned long long vs1 = splat2(v.y);
            const unsigned long long vs2 = splat2(v.z);
            const unsigned long long vs3 = splat2(v.w);
            // j-paired A broadcasts: one LDS.128 covers samples 2jp, 2jp+1
            const ulonglong2* ap =
                reinterpret_cast<const ulonglong2*>(&sA[rbase + r][0]);
            #pragma unroll
            for (int jp = 0; jp < KK / 2; ++jp) {
                const ulonglong2 a2 = ap[jp];
                ffma2(acc[2 * jp][0], a2.x, vs0);
                ffma2(acc[2 * jp][1], a2.x, vs1);
                ffma2(acc[2 * jp][2], a2.x, vs2);
                ffma2(acc[2 * jp][3], a2.x, vs3);
                ffma2(acc[2 * jp + 1][0], a2.y, vs0);
                ffma2(acc[2 * jp + 1][1], a2.y, vs1);
                ffma2(acc[2 * jp + 1][2], a2.y, vs2);
                ffma2(acc[2 * jp + 1][3], a2.y, vs3);
            }
            if (KK & 1) {
                const unsigned long long aj = sA[rbase + r][KK - 1];
                ffma2(acc[KK - 1][0], aj, vs0);
                ffma2(acc[KK - 1][1], aj, vs1);
                ffma2(acc[KK - 1][2], aj, vs2);
                ffma2(acc[KK - 1][3], aj, vs3);
            }
        }
        __syncthreads();   // buffer use_b fully consumed
        if (s + 2 < NSTAGE_TOT && t == 0) {
            mbar_expect_tx(mb0_u32 + 8 * iss_b, STAGE_BYTES);
            bulk_ld(sbuf0_u32 + iss_b * STAGE_BYTES,
                    slice + (size_t)(s + 2) * ROWS_PER_STAGE * 512,
                    STAGE_BYTES, mb0_u32 + 8 * iss_b);
        }
        if (++use_b == NBUF) { use_b = 0; use_ph ^= 1; }
        if (++iss_b == NBUF) { iss_b = 0; }
    }

    // epilogue: contract with C over thread's 4 r1 (=4*lane+c), reduce, store
    #pragma unroll
    for (int j = 0; j < KK; ++j) {
        const float* c = core2_t + (size_t)sI2[j] * 256;
        const float4 cA = *reinterpret_cast<const float4*>(c + 8 * lane);
        const float4 cB = *reinterpret_cast<const float4*>(c + 8 * lane + 4);
        float s00, s10, s01, s11, s02, s12, s03, s13;
        unpack2(acc[j][0], s00, s10);
        unpack2(acc[j][1], s01, s11);
        unpack2(acc[j][2], s02, s12);
        unpack2(acc[j][3], s03, s13);
        float o00 = s00 * cA.x + s01 * cA.z + s02 * cB.x + s03 * cB.z;
        float o01 = s00 * cA.y + s01 * cA.w + s02 * cB.y + s03 * cB.w;
        float o10 = s10 * cA.x + s11 * cA.z + s12 * cB.x + s13 * cB.z;
        float o11 = s10 * cA.y + s11 * cA.w + s12 * cB.y + s13 * cB.w;
        #pragma unroll
        for (int off = 16; off; off >>= 1) {
            o00 += __shfl_down_sync(0xffffffffu, o00, off);
            o01 += __shfl_down_sync(0xffffffffu, o01, off);
            o10 += __shfl_down_sync(0xffffffffu, o10, off);
            o11 += __shfl_down_sync(0xffffffffu, o11, off);
        }
        if (lane == 0) {
            float* op = out + (size_t)sSid[j] * 16;
            op[w * 2 + 0]     = o00;   // q0=0, q1=w, q2=0
            op[w * 2 + 1]     = o01;   // q0=0, q1=w, q2=1
            op[8 + w * 2 + 0] = o10;   // q0=1, q1=w, q2=0
            op[8 + w * 2 + 1] = o11;   // q0=1, q1=w, q2=1
        }
    }
}

// --------------------------------------------------------------- kernel ----
__global__ __launch_bounds__(128, 6) void tt_kernel(
    const int* __restrict__ lS_i,         // [T*B] int32
    const float* __restrict__ core0,      // [T, P0, 256]
    const float* __restrict__ core1,      // [T, P1, 65536]
    const float* __restrict__ core2,      // [T, P2, 256]
    float* __restrict__ out,              // [T*B, 16]
    int batch)
{
    const int bucket = blockIdx.x;        // 0..431
    const int table  = bucket / P1;
    const int i1t    = bucket % P1;
    const int p      = blockIdx.y;        // pass 0..NP-1

    const int t    = threadIdx.x;         // 0..127
    const int lane = t & 31;
    const int w    = t >> 5;

    __shared__ __align__(16) float sbuf[NBUF * ROWS_PER_STAGE * 512];  // 24KB
    __shared__ __align__(16) unsigned long long sA[128][SMAXU];        // 6KB
    __shared__ __align__(8) unsigned long long sMbar[NBUF];
    __shared__ int sList[LISTCAP];
    __shared__ int sWarpTot[4];
    __shared__ int sSid[SMAXU], sI2[SMAXU];

    const uint32_t mb0_u32   = smem_u32(&sMbar[0]);
    const uint32_t sbuf0_u32 = smem_u32(sbuf);

    if (t == 0) {
        #pragma unroll
        for (int b = 0; b < NBUF; ++b) mbar_init(mb0_u32 + 8 * b, 1);
    }

    // ---- scan this table's indices for i1 == i1t (canonical order) ----
    const int per = batch >> 7;           // 8 for batch=1024
    const int s0  = table * batch + t * per;
    int sel[8];
    int cnt = 0;
    {
        const int4* ip = reinterpret_cast<const int4*>(lS_i + s0);
        #pragma unroll
        for (int q = 0; q < 2; ++q) {
            const int4 u = ip[q];
            const int v[4] = {u.x, u.y, u.z, u.w};
            #pragma unroll
            for (int j = 0; j < 4; ++j) {
                if ((v[j] / P2) % P1 == i1t) sel[cnt++] = s0 + q * 4 + j;
            }
        }
    }
    // warp inclusive scan of cnt
    int inc = cnt;
    #pragma unroll
    for (int off = 1; off < 32; off <<= 1) {
        const int v = __shfl_up_sync(0xffffffffu, inc, off);
        if (lane >= off) inc += v;
    }
    if (lane == 31) sWarpTot[w] = inc;
    __syncthreads();
    int warpBase = 0;
    #pragma unroll
    for (int ww = 0; ww < 4; ++ww)
        if (ww < w) warpBase += sWarpTot[ww];
    const int ktot = sWarpTot[0] + sWarpTot[1] + sWarpTot[2] + sWarpTot[3];
    const int excl = warpBase + inc - cnt;
    for (int j = 0; j < cnt; ++j) {
        const int pos = excl + j;
        if (pos < LISTCAP) sList[pos] = sel[j];
    }
    __syncthreads();

    const int kk = min(SMAXU, ktot - p * SMAXU);
    if (kk <= 0) return;

    const float* slice = core1 + ((size_t)bucket) * 65536;

    // prologue: issue 2 stages immediately (overlaps with sA setup)
    if (t == 0) {
        #pragma unroll
        for (int s = 0; s < 2; ++s) {
            mbar_expect_tx(mb0_u32 + 8 * s, STAGE_BYTES);
            bulk_ld(sbuf0_u32 + s * STAGE_BYTES,
                    slice + (size_t)s * ROWS_PER_STAGE * 512,
                    STAGE_BYTES, mb0_u32 + 8 * s);
        }
    }

    if (t < kk) {
        const int sid = sList[p * SMAXU + t];
        sSid[t] = sid;
        sI2[t]  = lS_i[sid] % P2;
    }

    // A slices: thread t covers row r=t, all kk samples
    #pragma unroll
    for (int j = 0; j < SMAXU; ++j) {
        unsigned long long pack = 0ull;
        if (j < kk) {
            const int sid = sList[p * SMAXU + j];
            const int id  = lS_i[sid];
            const int i0  = id / (P1 * P2);
            const float* a = core0 + ((size_t)(table * P0 + i0)) * 256;
            const unsigned int a0 = __float_as_uint(a[t]);
            const unsigned int a1 = __float_as_uint(a[t + 128]);
            pack = (unsigned long long)a0 | ((unsigned long long)a1 << 32);
        }
        sA[t][j] = pack;
    }
    __syncthreads();   // sA + metadata + mbar init visible to all

    const float* core2_t = core2 + (size_t)table * P2 * 256;

    switch (kk) {
        case 6: run_unit<6>(slice, sbuf, sbuf0_u32, mb0_u32, sA, sSid, sI2, core2_t, out, t, lane, w); break;
        case 5: run_unit<5>(slice, sbuf, sbuf0_u32, mb0_u32, sA, sSid, sI2, core2_t, out, t, lane, w); break;
        case 4: run_unit<4>(slice, sbuf, sbuf0_u32, mb0_u32, sA, sSid, sI2, core2_t, out, t, lane, w); break;
        case 3: run_unit<3>(slice, sbuf, sbuf0_u32, mb0_u32, sA, sSid, sI2, core2_t, out, t, lane, w); break;
        case 2: run_unit<2>(slice, sbuf, sbuf0_u32, mb0_u32, sA, sSid, sI2, core2_t, out, t, lane, w); break;
        default: run_unit<1>(slice, sbuf, sbuf0_u32, mb0_u32, sA, sSid, sI2, core2_t, out, t, lane, w); break;
    }
}

// --------------------------------------------------------------- launch ----
extern "C" void kernel_launch(void* const* d_in, const int* in_sizes, int n_in,
                              void* d_out, int out_size) {
    const int*   lS_i  = (const int*)d_in[0];
    const float* core0 = (const float*)d_in[1];
    const float* core1 = (const float*)d_in[2];
    const float* core2 = (const float*)d_in[3];
    float*       out   = (float*)d_out;

    const int n_samples = in_sizes[0];        // TABLES * batch = 2048
    const int batch     = n_samples / TABLES;

    dim3 grid(TABLES * P1, NP);
    tt_kernel<<<grid, 128>>>(lS_i, core0, core1, core2, out, batch);
}